// round 6
// baseline (speedup 1.0000x reference)
#include <cuda_runtime.h>
#include <cuda_fp16.h>
#include <math.h>

// Problem shape (fixed by the dataset)
#define N_NODES 100000
#define N_EDGES 3200000
#define LATENT  64            // floats per row
#define H2      (LATENT/2)    // half2 per row = 32 (one per lane)

// ---------------- scratch (no allocs allowed) ----------------
__device__ int     g_deg[N_NODES];
__device__ int     g_next[N_NODES];            // running fill cursor (starts at rowptr)
__device__ int     g_rowptr[N_NODES + 1];
__device__ int2    g_cv[N_EDGES];              // .x = col, .y = val (bitcast float)
__device__ __half2 g_xh[N_NODES * H2];         // fp16-staged x
__device__ __half2 g_tmph[N_NODES * H2];       // fp16 first-hop result

// ---------------- stage x -> fp16 and zero histogram (fused) ----------------
__global__ void stage_kernel(const float* __restrict__ x) {
    int i = blockIdx.x * blockDim.x + threadIdx.x;
    int stride = gridDim.x * blockDim.x;
    const float2* __restrict__ x2 = reinterpret_cast<const float2*>(x);
    for (int k = i; k < N_NODES * H2; k += stride) {
        float2 v = x2[k];
        g_xh[k] = __floats2half2_rn(v.x, v.y);
    }
    for (int k = i; k < N_NODES; k += stride) g_deg[k] = 0;
}

__global__ void histogram_kernel(const int* __restrict__ rows) {
    int i = blockIdx.x * blockDim.x + threadIdx.x;
    int stride = gridDim.x * blockDim.x;
    for (int e = i; e < N_EDGES; e += stride)
        atomicAdd(&g_deg[rows[e]], 1);
}

// single-block exclusive scan of g_deg -> g_rowptr AND g_next (N=100k, 1024 threads)
__global__ void scan_kernel() {
    __shared__ int sums[1024];
    const int t = threadIdx.x;
    const int chunk = (N_NODES + 1023) / 1024;   // 98
    int start = t * chunk;
    int end   = start + chunk; if (end > N_NODES) end = N_NODES;
    if (start > N_NODES) start = N_NODES;

    int s = 0;
    for (int i = start; i < end; i++) s += g_deg[i];
    sums[t] = s;
    __syncthreads();
    for (int off = 1; off < 1024; off <<= 1) {
        int v = (t >= off) ? sums[t - off] : 0;
        __syncthreads();
        sums[t] += v;
        __syncthreads();
    }
    int run = (t == 0) ? 0 : sums[t - 1];
    for (int i = start; i < end; i++) {
        g_rowptr[i] = run;
        g_next[i]   = run;
        run += g_deg[i];
    }
    if (end == N_NODES) g_rowptr[N_NODES] = run;   // == N_EDGES
}

__global__ void scatter_kernel(const int* __restrict__ rows,
                               const int* __restrict__ cols,
                               const float* __restrict__ vals) {
    int i = blockIdx.x * blockDim.x + threadIdx.x;
    int stride = gridDim.x * blockDim.x;
    for (int e = i; e < N_EDGES; e += stride) {
        int r = rows[e];
        int pos = atomicAdd(&g_next[r], 1);
        int2 cv; cv.x = cols[e]; cv.y = __float_as_int(vals[e]);
        g_cv[pos] = cv;
    }
}

// ---------------- SpMM: warp per row, lane holds half2; edge data via uniform LDG ----------------
__device__ __forceinline__ float2 spmm_row_h(int row, int lane,
                                             const __half2* __restrict__ srch) {
    const int s = g_rowptr[row];
    const int e = g_rowptr[row + 1];
    float2 acc0 = make_float2(0.f, 0.f);
    float2 acc1 = make_float2(0.f, 0.f);

    int b = s;
    #pragma unroll 1
    for (; b + 2 <= e; b += 2) {
        int2 cv0 = __ldg(&g_cv[b]);       // warp-uniform: 1 sector, L1-resident line
        int2 cv1 = __ldg(&g_cv[b + 1]);
        __half2 h0 = __ldg(&srch[cv0.x * H2 + lane]);
        __half2 h1 = __ldg(&srch[cv1.x * H2 + lane]);
        float v0 = __int_as_float(cv0.y);
        float v1 = __int_as_float(cv1.y);
        float2 f0 = __half22float2(h0);
        float2 f1 = __half22float2(h1);
        acc0.x = fmaf(v0, f0.x, acc0.x);
        acc0.y = fmaf(v0, f0.y, acc0.y);
        acc1.x = fmaf(v1, f1.x, acc1.x);
        acc1.y = fmaf(v1, f1.y, acc1.y);
    }
    if (b < e) {
        int2 cv = __ldg(&g_cv[b]);
        __half2 h = __ldg(&srch[cv.x * H2 + lane]);
        float v = __int_as_float(cv.y);
        float2 f = __half22float2(h);
        acc0.x = fmaf(v, f.x, acc0.x);
        acc0.y = fmaf(v, f.y, acc0.y);
    }
    return make_float2(acc0.x + acc1.x, acc0.y + acc1.y);
}

__global__ void __launch_bounds__(256) hop1_kernel() {
    int gw   = (blockIdx.x * blockDim.x + threadIdx.x) >> 5;
    int lane = threadIdx.x & 31;
    if (gw >= N_NODES) return;
    float2 acc = spmm_row_h(gw, lane, g_xh);
    g_tmph[gw * H2 + lane] = __floats2half2_rn(acc.x, acc.y);
}

__global__ void __launch_bounds__(256) hop2_kernel(const float* __restrict__ x,
                                                   const float* __restrict__ alpha,
                                                   float* __restrict__ out) {
    int gw   = (blockIdx.x * blockDim.x + threadIdx.x) >> 5;
    int lane = threadIdx.x & 31;
    if (gw >= N_NODES) return;
    float2 acc = spmm_row_h(gw, lane, g_tmph);
    float sig = 1.0f / (1.0f + __expf(-alpha[gw]));
    float2 xr = reinterpret_cast<const float2*>(x)[(size_t)gw * H2 + lane];
    float2 r;
    r.x = sig * acc.x - xr.x;
    r.y = sig * acc.y - xr.y;
    reinterpret_cast<float2*>(out)[(size_t)gw * H2 + lane] = r;
}

// ---------------- launch ----------------
extern "C" void kernel_launch(void* const* d_in, const int* in_sizes, int n_in,
                              void* d_out, int out_size) {
    // inputs (metadata order): t, x[N,64], alpha[N], edge_rows[E], edge_cols[E], edge_vals[E]
    const float* x     = (const float*)d_in[1];
    const float* alpha = (const float*)d_in[2];
    const int*   erow  = (const int*)d_in[3];
    const int*   ecol  = (const int*)d_in[4];
    const float* evals = (const float*)d_in[5];
    float* out = (float*)d_out;

    stage_kernel<<<1184, 512>>>(x);                 // x -> fp16 + zero histogram
    histogram_kernel<<<1184, 512>>>(erow);
    scan_kernel<<<1, 1024>>>();
    scatter_kernel<<<1184, 512>>>(erow, ecol, evals);

    const int threads = 256;
    const int blocks  = (N_NODES * 32 + threads - 1) / threads;  // 12500
    hop1_kernel<<<blocks, threads>>>();
    hop2_kernel<<<blocks, threads>>>(x, alpha, out);
}

// round 8
// speedup vs baseline: 1.9627x; 1.9627x over previous
#include <cuda_runtime.h>
#include <cuda_fp16.h>
#include <math.h>

// Problem shape (fixed by the dataset)
#define N_NODES 100000
#define N_EDGES 3200000
#define LATENT  64            // floats per row
#define H2      (LATENT/2)    // half2 per row = 32 (one per lane)

#define SCAN_BLK 1024
#define N_TILES  ((N_NODES + SCAN_BLK - 1) / SCAN_BLK)   // 98

// ---------------- scratch (no allocs allowed) ----------------
__device__ int     g_deg[N_NODES];
__device__ int     g_next[N_NODES];            // fill cursor (starts at rowptr)
__device__ int     g_rowptr[N_NODES + 1];
__device__ int     g_tilesum[N_TILES];
__device__ int     g_tileoff[N_TILES];
__device__ int2    g_cv[N_EDGES];              // .x = col, .y = val (bitcast float)
__device__ __half2 g_xh[N_NODES * H2];         // fp16-staged x
__device__ __half2 g_tmph[N_NODES * H2];       // fp16 first-hop result

// ---------------- stage x -> fp16 and zero histogram (fused) ----------------
__global__ void stage_kernel(const float* __restrict__ x) {
    int i = blockIdx.x * blockDim.x + threadIdx.x;
    int stride = gridDim.x * blockDim.x;
    const float2* __restrict__ x2 = reinterpret_cast<const float2*>(x);
    for (int k = i; k < N_NODES * H2; k += stride) {
        float2 v = x2[k];
        g_xh[k] = __floats2half2_rn(v.x, v.y);
    }
    for (int k = i; k < N_NODES; k += stride) g_deg[k] = 0;
}

__global__ void histogram_kernel(const int* __restrict__ rows) {
    int i = blockIdx.x * blockDim.x + threadIdx.x;
    int stride = gridDim.x * blockDim.x;
    for (int e = i; e < N_EDGES; e += stride)
        atomicAdd(&g_deg[rows[e]], 1);
}

// ---------------- parallel 3-phase exclusive scan (coalesced) ----------------
__global__ void __launch_bounds__(SCAN_BLK) tile_reduce_kernel() {
    __shared__ int wsum[32];
    int i = blockIdx.x * SCAN_BLK + threadIdx.x;
    int v = (i < N_NODES) ? __ldg(&g_deg[i]) : 0;
    #pragma unroll
    for (int o = 16; o; o >>= 1) v += __shfl_down_sync(0xffffffffu, v, o);
    int w = threadIdx.x >> 5, l = threadIdx.x & 31;
    if (l == 0) wsum[w] = v;
    __syncthreads();
    if (w == 0) {
        int s = wsum[l];
        #pragma unroll
        for (int o = 16; o; o >>= 1) s += __shfl_down_sync(0xffffffffu, s, o);
        if (l == 0) g_tilesum[blockIdx.x] = s;
    }
}

__global__ void tile_offset_kernel() {   // 1 block, 128 threads
    __shared__ int sh[128];
    int t = threadIdx.x;
    int v = (t < N_TILES) ? g_tilesum[t] : 0;
    sh[t] = v;
    __syncthreads();
    for (int o = 1; o < 128; o <<= 1) {
        int u = (t >= o) ? sh[t - o] : 0;
        __syncthreads();
        sh[t] += u;
        __syncthreads();
    }
    if (t < N_TILES) g_tileoff[t] = sh[t] - v;            // exclusive
    if (t == N_TILES - 1) g_rowptr[N_NODES] = sh[t];      // == N_EDGES
}

__global__ void __launch_bounds__(SCAN_BLK) tile_scan_kernel() {
    __shared__ int wsum[32];
    int b = blockIdx.x;
    int i = b * SCAN_BLK + threadIdx.x;
    int v = (i < N_NODES) ? __ldg(&g_deg[i]) : 0;
    int l = threadIdx.x & 31, w = threadIdx.x >> 5;
    int xi = v;                                            // inclusive warp scan
    #pragma unroll
    for (int o = 1; o < 32; o <<= 1) {
        int u = __shfl_up_sync(0xffffffffu, xi, o);
        if (l >= o) xi += u;
    }
    if (l == 31) wsum[w] = xi;
    __syncthreads();
    if (w == 0) {
        int s = wsum[l];
        #pragma unroll
        for (int o = 1; o < 32; o <<= 1) {
            int u = __shfl_up_sync(0xffffffffu, s, o);
            if (l >= o) s += u;
        }
        wsum[l] = s;
    }
    __syncthreads();
    int excl = xi - v + (w ? wsum[w - 1] : 0) + g_tileoff[b];
    if (i < N_NODES) { g_rowptr[i] = excl; g_next[i] = excl; }
}

__global__ void scatter_kernel(const int* __restrict__ rows,
                               const int* __restrict__ cols,
                               const float* __restrict__ vals) {
    int i = blockIdx.x * blockDim.x + threadIdx.x;
    int stride = gridDim.x * blockDim.x;
    for (int e = i; e < N_EDGES; e += stride) {
        int r = rows[e];
        int pos = atomicAdd(&g_next[r], 1);
        int2 cv; cv.x = cols[e]; cv.y = __float_as_int(vals[e]);
        g_cv[pos] = cv;
    }
}

// ---------------- SpMM (R5 proven): warp per row, batch+SHFL broadcast, unroll 8 ----------------
__device__ __forceinline__ float2 spmm_row_h(int row, int lane,
                                             const __half2* __restrict__ srch) {
    const int s = g_rowptr[row];
    const int e = g_rowptr[row + 1];
    float2 acc = make_float2(0.f, 0.f);

    int b = s;
    for (; b + 32 <= e; b += 32) {
        int2 cv = __ldg(&g_cv[b + lane]);
        #pragma unroll 8
        for (int j = 0; j < 32; j++) {
            int   cj = __shfl_sync(0xffffffffu, cv.x, j);
            float vj = __int_as_float(__shfl_sync(0xffffffffu, cv.y, j));
            __half2 h = __ldg(&srch[cj * H2 + lane]);
            float2 xf = __half22float2(h);
            acc.x = fmaf(vj, xf.x, acc.x);
            acc.y = fmaf(vj, xf.y, acc.y);
        }
    }
    if (b < e) {
        int idx = b + lane;
        int2 cv = make_int2(0, 0);
        if (idx < e) cv = __ldg(&g_cv[idx]);
        int m = e - b;
        for (int j = 0; j < m; j++) {
            int   cj = __shfl_sync(0xffffffffu, cv.x, j);
            float vj = __int_as_float(__shfl_sync(0xffffffffu, cv.y, j));
            __half2 h = __ldg(&srch[cj * H2 + lane]);
            float2 xf = __half22float2(h);
            acc.x = fmaf(vj, xf.x, acc.x);
            acc.y = fmaf(vj, xf.y, acc.y);
        }
    }
    return acc;
}

__global__ void __launch_bounds__(256) hop1_kernel() {
    int gw   = (blockIdx.x * blockDim.x + threadIdx.x) >> 5;
    int lane = threadIdx.x & 31;
    if (gw >= N_NODES) return;
    float2 acc = spmm_row_h(gw, lane, g_xh);
    g_tmph[gw * H2 + lane] = __floats2half2_rn(acc.x, acc.y);
}

__global__ void __launch_bounds__(256) hop2_kernel(const float* __restrict__ x,
                                                   const float* __restrict__ alpha,
                                                   float* __restrict__ out) {
    int gw   = (blockIdx.x * blockDim.x + threadIdx.x) >> 5;
    int lane = threadIdx.x & 31;
    if (gw >= N_NODES) return;
    float2 acc = spmm_row_h(gw, lane, g_tmph);
    float sig = 1.0f / (1.0f + __expf(-alpha[gw]));
    float2 xr = reinterpret_cast<const float2*>(x)[(size_t)gw * H2 + lane];
    float2 r;
    r.x = sig * acc.x - xr.x;
    r.y = sig * acc.y - xr.y;
    reinterpret_cast<float2*>(out)[(size_t)gw * H2 + lane] = r;
}

// ---------------- launch ----------------
extern "C" void kernel_launch(void* const* d_in, const int* in_sizes, int n_in,
                              void* d_out, int out_size) {
    // inputs (metadata order): t, x[N,64], alpha[N], edge_rows[E], edge_cols[E], edge_vals[E]
    const float* x     = (const float*)d_in[1];
    const float* alpha = (const float*)d_in[2];
    const int*   erow  = (const int*)d_in[3];
    const int*   ecol  = (const int*)d_in[4];
    const float* evals = (const float*)d_in[5];
    float* out = (float*)d_out;

    stage_kernel<<<1184, 512>>>(x);                 // x -> fp16 + zero histogram
    histogram_kernel<<<1184, 512>>>(erow);
    tile_reduce_kernel<<<N_TILES, SCAN_BLK>>>();
    tile_offset_kernel<<<1, 128>>>();
    tile_scan_kernel<<<N_TILES, SCAN_BLK>>>();
    scatter_kernel<<<1184, 512>>>(erow, ecol, evals);

    const int threads = 256;
    const int blocks  = (N_NODES * 32 + threads - 1) / threads;  // 12500
    hop1_kernel<<<blocks, threads>>>();
    hop2_kernel<<<blocks, threads>>>(x, alpha, out);
}